// round 1
// baseline (speedup 1.0000x reference)
#include <cuda_runtime.h>
#include <cuda_bf16.h>

// ---------------- scratch (static device memory only; no allocation) ----------------
__device__ float g_A1[64 * 4899];        // branch-a pooled features
__device__ float g_h1[64 * 1000];
__device__ float g_h2[64 * 500];
__device__ float g_a3[64 * 9];
__device__ float g_yb[64 * 2 * 4900];    // branch-b stage-1 output
__device__ float g_cat[64 * 15506];      // concat buffer
__device__ float g_z1[64 * 8000];
__device__ float g_z2[64 * 2000];
__device__ float g_part[16 * 64 * 8000]; // split-K partials (32.8 MB)

// ---------------- branch a front: conv3x3(pad1) + relu + maxpool(2,2)s(1,1) ----------
__global__ void k_a_front(const float* __restrict__ x1, const float* __restrict__ w1,
                          const float* __restrict__ b1) {
    int idx = blockIdx.x * blockDim.x + threadIdx.x;
    if (idx >= 64 * 4899) return;
    int b = idx / 4899, j = idx % 4899;
    const float* X = x1 + b * 9800;
    float r0[4], r1[4];
#pragma unroll
    for (int d = 0; d < 4; d++) {
        int c = j - 1 + d;
        bool ok = (c >= 0 && c < 4900);
        r0[d] = ok ? __ldg(&X[c]) : 0.f;
        r1[d] = ok ? __ldg(&X[4900 + c]) : 0.f;
    }
    float W[9];
#pragma unroll
    for (int i = 0; i < 9; i++) W[i] = __ldg(&w1[i]);
    float bb = __ldg(&b1[0]);
    float m = -1e30f;
#pragma unroll
    for (int o = 0; o < 2; o++) {
        // conv at h=0 (x rows 0,1 with w1 rows 1,2)
        float c0 = bb + W[3]*r0[o] + W[4]*r0[o+1] + W[5]*r0[o+2]
                      + W[6]*r1[o] + W[7]*r1[o+1] + W[8]*r1[o+2];
        // conv at h=1 (x rows 0,1 with w1 rows 0,1)
        float c1 = bb + W[0]*r0[o] + W[1]*r0[o+1] + W[2]*r0[o+2]
                      + W[3]*r1[o] + W[4]*r1[o+1] + W[5]*r1[o+2];
        m = fmaxf(m, fmaxf(c0, c1));
    }
    g_A1[idx] = fmaxf(m, 0.f);
}

// ---------------- generic split-K GEMM: C_part = A(64xK) * W(KxN) ---------------------
#define KT 16
#define AS_STRIDE 68

__global__ __launch_bounds__(256, 2)
void k_gemm(const float* __restrict__ A, const float* __restrict__ W,
            float* __restrict__ part, int K, int N, int kSplit) {
    __shared__ float As[KT * AS_STRIDE];
    __shared__ float Ws[KT * 256];
    int n0 = blockIdx.x * 256;
    int ks = blockIdx.y;
    int kLen = (K + kSplit - 1) / kSplit;
    int kbeg = ks * kLen;
    int kend = min(K, kbeg + kLen);
    int t = threadIdx.x;
    int mg = t >> 5, nt = t & 31;
    int m0 = mg * 8;
    unsigned long long acc[4][8];
#pragma unroll
    for (int p = 0; p < 4; p++)
#pragma unroll
        for (int i = 0; i < 8; i++) acc[p][i] = 0ULL;

    int am = t >> 2;
    int aq = (t & 3) * 4;

    for (int k0 = kbeg; k0 < kend; k0 += KT) {
        // A tile -> shared (transposed, [k][m])
#pragma unroll
        for (int i = 0; i < 4; i++) {
            int kg = k0 + aq + i;
            As[(aq + i) * AS_STRIDE + am] = (kg < kend) ? A[am * K + kg] : 0.f;
        }
        // W tile -> shared ([k][n])
#pragma unroll
        for (int r = 0; r < 4; r++) {
            int lin = t + 256 * r;
            int kk = lin >> 6;
            int n4 = (lin & 63) << 2;
            int kg = k0 + kk;
            int ng = n0 + n4;
            float4 v = make_float4(0.f, 0.f, 0.f, 0.f);
            if (kg < kend) {
                if (ng + 3 < N) {
                    v = *reinterpret_cast<const float4*>(&W[kg * N + ng]);
                } else {
                    if (ng + 0 < N) v.x = W[kg * N + ng + 0];
                    if (ng + 1 < N) v.y = W[kg * N + ng + 1];
                    if (ng + 2 < N) v.z = W[kg * N + ng + 2];
                    if (ng + 3 < N) v.w = W[kg * N + ng + 3];
                }
            }
            *reinterpret_cast<float4*>(&Ws[kk * 256 + n4]) = v;
        }
        __syncthreads();
#pragma unroll
        for (int kk = 0; kk < KT; kk++) {
            ulonglong2 a01 = *reinterpret_cast<const ulonglong2*>(&As[kk * AS_STRIDE + m0]);
            ulonglong2 a23 = *reinterpret_cast<const ulonglong2*>(&As[kk * AS_STRIDE + m0 + 4]);
            unsigned long long av[4] = {a01.x, a01.y, a23.x, a23.y};
            float4 w03 = *reinterpret_cast<const float4*>(&Ws[kk * 256 + nt * 4]);
            float4 w47 = *reinterpret_cast<const float4*>(&Ws[kk * 256 + 128 + nt * 4]);
            float wv[8] = {w03.x, w03.y, w03.z, w03.w, w47.x, w47.y, w47.z, w47.w};
#pragma unroll
            for (int i = 0; i < 8; i++) {
                unsigned long long ww;
                unsigned int wu = __float_as_uint(wv[i]);
                asm("mov.b64 %0, {%1,%1};" : "=l"(ww) : "r"(wu));
#pragma unroll
                for (int p = 0; p < 4; p++) {
                    asm("fma.rn.f32x2 %0, %1, %2, %0;"
                        : "+l"(acc[p][i]) : "l"(av[p]), "l"(ww));
                }
            }
        }
        __syncthreads();
    }
    float* out = part + (size_t)ks * 64 * N;
#pragma unroll
    for (int i = 0; i < 8; i++) {
        int ng = n0 + ((i < 4) ? nt * 4 + i : 128 + nt * 4 + (i - 4));
        if (ng < N) {
#pragma unroll
            for (int p = 0; p < 4; p++) {
                unsigned int lo, hi;
                asm("mov.b64 {%0,%1}, %2;" : "=r"(lo), "=r"(hi) : "l"(acc[p][i]));
                out[(m0 + 2 * p) * N + ng]     = __uint_as_float(lo);
                out[(m0 + 2 * p + 1) * N + ng] = __uint_as_float(hi);
            }
        }
    }
}

// ---------------- split-K reduce + bias (+relu) ----------------------------------------
__global__ void k_reduce(const float* __restrict__ bias, float* __restrict__ C,
                         int N, int S, int doRelu) {
    int idx = blockIdx.x * blockDim.x + threadIdx.x;
    if (idx >= 64 * N) return;
    float s = bias[idx % N];
    const float* p = g_part + idx;
    long stride = (long)64 * N;
    for (int j = 0; j < S; j++) s += p[j * stride];
    C[idx] = doRelu ? fmaxf(s, 0.f) : s;
}

// ---------------- tiny GEMM: h2(64x500) @ Wc(500x9) + bc -> a3 -------------------------
__global__ void k_gemm3(const float* __restrict__ Wc, const float* __restrict__ bc) {
    int b = blockIdx.x / 9, n = blockIdx.x % 9;
    int lane = threadIdx.x;
    float s = 0.f;
    for (int k = lane; k < 500; k += 32) s += g_h2[b * 500 + k] * Wc[k * 9 + n];
#pragma unroll
    for (int o = 16; o; o >>= 1) s += __shfl_xor_sync(0xffffffff, s, o);
    if (lane == 0) g_a3[b * 9 + n] = s + bc[n];
}

// ---------------- dynamic per-sample conv + relu + pool(2,2)s(2,2) -> cat[:, :2450] ----
__global__ void k_dyn(const float* __restrict__ x1, const float* __restrict__ lw,
                      const float* __restrict__ lb) {
    __shared__ float sdw[9];
    __shared__ float slb;
    int b = blockIdx.x;
    int tid = threadIdx.x;
    if (tid < 9) sdw[tid] = lw[b * 9 + tid] * g_a3[b * 9 + tid];
    if (tid == 9) slb = lb[b];
    __syncthreads();
    int t = blockIdx.y * blockDim.x + tid;
    if (t >= 2450) return;
    const float* X = x1 + b * 9800;
    float r0[4], r1[4];
    int base = 2 * t - 1;
#pragma unroll
    for (int d = 0; d < 4; d++) {
        int c = base + d;
        bool ok = (c >= 0 && c < 4900);
        r0[d] = ok ? X[c] : 0.f;
        r1[d] = ok ? X[4900 + c] : 0.f;
    }
    float m = -1e30f;
#pragma unroll
    for (int o = 0; o < 2; o++) {
        float c0 = slb + sdw[3]*r0[o] + sdw[4]*r0[o+1] + sdw[5]*r0[o+2]
                       + sdw[6]*r1[o] + sdw[7]*r1[o+1] + sdw[8]*r1[o+2];
        float c1 = slb + sdw[0]*r0[o] + sdw[1]*r0[o+1] + sdw[2]*r0[o+2]
                       + sdw[3]*r1[o] + sdw[4]*r1[o+1] + sdw[5]*r1[o+2];
        m = fmaxf(m, fmaxf(c0, c1));
    }
    g_cat[b * 15506 + t] = fmaxf(m, 0.f);
}

// ---------------- branch b stage 1: conv2x2(pad1)+relu+pool(2,2)s(1,1) -> yb -----------
__global__ void k_b1(const float* __restrict__ x2, const float* __restrict__ w5,
                     const float* __restrict__ b5) {
    int idx = blockIdx.x * blockDim.x + threadIdx.x;
    if (idx >= 64 * 4900) return;
    int b = idx / 4900, w = idx % 4900;
    const float* X = x2 + b * 9800;
    float x0[3], x1v[3];
#pragma unroll
    for (int d = 0; d < 3; d++) {
        int c = w - 1 + d;
        bool ok = (c >= 0 && c < 4900);
        x0[d]  = ok ? X[c] : 0.f;
        x1v[d] = ok ? X[4900 + c] : 0.f;
    }
    float W00 = __ldg(&w5[0]), W01 = __ldg(&w5[1]), W10 = __ldg(&w5[2]), W11 = __ldg(&w5[3]);
    float bb = __ldg(&b5[0]);
    float c0a = bb + W10*x0[0] + W11*x0[1];
    float c0b = bb + W10*x0[1] + W11*x0[2];
    float c1a = bb + W00*x0[0] + W01*x0[1] + W10*x1v[0] + W11*x1v[1];
    float c1b = bb + W00*x0[1] + W01*x0[2] + W10*x1v[1] + W11*x1v[2];
    float c2a = bb + W00*x1v[0] + W01*x1v[1];
    float c2b = bb + W00*x1v[1] + W01*x1v[2];
    float y0 = fmaxf(fmaxf(c0a, c0b), fmaxf(c1a, c1b));
    float y1 = fmaxf(fmaxf(c1a, c1b), fmaxf(c2a, c2b));
    g_yb[b * 9800 + w]        = fmaxf(y0, 0.f);
    g_yb[b * 9800 + 4900 + w] = fmaxf(y1, 0.f);
}

// ---------------- branch b stage 2: conv(32,2x2,s2)+relu+pool(1,6)s6 -> cat[:,2450:] ----
__global__ void k_b2(const float* __restrict__ w6, const float* __restrict__ b6) {
    __shared__ float sy[2][96];
    __shared__ float sw[128];
    __shared__ float sb[32];
    int b = blockIdx.x;
    int u0 = blockIdx.y * 8;
    int tid = threadIdx.y * 32 + threadIdx.x;
    int c0 = u0 * 12;
    if (tid < 192) {
        int row = tid / 96, cc = tid % 96;
        sy[row][cc] = g_yb[b * 9800 + row * 4900 + c0 + cc];
    }
    if (tid < 128) sw[tid] = w6[tid];
    if (tid < 32)  sb[tid] = b6[tid];
    __syncthreads();
    int c = threadIdx.x, ul = threadIdx.y;
    int base = ul * 12;
    float w00 = sw[c*4], w01 = sw[c*4+1], w10 = sw[c*4+2], w11 = sw[c*4+3];
    float best = -1e30f;
#pragma unroll
    for (int r = 0; r < 6; r++) {
        float v = sb[c] + sy[0][base+2*r]*w00 + sy[0][base+2*r+1]*w01
                        + sy[1][base+2*r]*w10 + sy[1][base+2*r+1]*w11;
        best = fmaxf(best, v);
    }
    g_cat[b * 15506 + 2450 + c * 408 + (u0 + ul)] = fmaxf(best, 0.f);
}

// ---------------- final tiny GEMM: z2(64x2000) @ Wf3(2000x2) + bf3 -> out --------------
__global__ void k_f3(const float* __restrict__ Wf3, const float* __restrict__ bf3,
                     float* __restrict__ out) {
    int b = blockIdx.x >> 1, n = blockIdx.x & 1;
    int lane = threadIdx.x;
    float s = 0.f;
    for (int k = lane; k < 2000; k += 32) s += g_z2[b * 2000 + k] * Wf3[k * 2 + n];
#pragma unroll
    for (int o = 16; o; o >>= 1) s += __shfl_xor_sync(0xffffffff, s, o);
    if (lane == 0) out[b * 2 + n] = s + bf3[n];
}

// ---------------- launch ----------------------------------------------------------------
extern "C" void kernel_launch(void* const* d_in, const int* in_sizes, int n_in,
                              void* d_out, int out_size) {
    const float* x1  = (const float*)d_in[0];
    const float* x2  = (const float*)d_in[1];
    const float* w1  = (const float*)d_in[2];
    const float* b1  = (const float*)d_in[3];
    const float* Wa  = (const float*)d_in[4];
    const float* ba  = (const float*)d_in[5];
    const float* Wb  = (const float*)d_in[6];
    const float* bb  = (const float*)d_in[7];
    const float* Wc  = (const float*)d_in[8];
    const float* bc  = (const float*)d_in[9];
    const float* lw  = (const float*)d_in[10];
    const float* lb  = (const float*)d_in[11];
    const float* w5  = (const float*)d_in[12];
    const float* b5  = (const float*)d_in[13];
    const float* w6  = (const float*)d_in[14];
    const float* b6  = (const float*)d_in[15];
    const float* Wf1 = (const float*)d_in[16];
    const float* bf1 = (const float*)d_in[17];
    const float* Wf2 = (const float*)d_in[18];
    const float* bf2 = (const float*)d_in[19];
    const float* Wf3 = (const float*)d_in[20];
    const float* bf3 = (const float*)d_in[21];
    float* out = (float*)d_out;

    float *A1, *h1, *h2, *cat, *z1, *z2, *part;
    cudaGetSymbolAddress((void**)&A1,  g_A1);
    cudaGetSymbolAddress((void**)&h1,  g_h1);
    cudaGetSymbolAddress((void**)&h2,  g_h2);
    cudaGetSymbolAddress((void**)&cat, g_cat);
    cudaGetSymbolAddress((void**)&z1,  g_z1);
    cudaGetSymbolAddress((void**)&z2,  g_z2);
    cudaGetSymbolAddress((void**)&part, g_part);

    // branch a front
    k_a_front<<<(64 * 4899 + 255) / 256, 256>>>(x1, w1, b1);
    // h1 = relu(A1 @ Wa + ba)
    k_gemm<<<dim3(4, 32), 256>>>(A1, Wa, part, 4899, 1000, 32);
    k_reduce<<<(64 * 1000 + 255) / 256, 256>>>(ba, h1, 1000, 32, 1);
    // h2 = relu(h1 @ Wb + bb)
    k_gemm<<<dim3(2, 32), 256>>>(h1, Wb, part, 1000, 500, 32);
    k_reduce<<<(64 * 500 + 255) / 256, 256>>>(bb, h2, 500, 32, 1);
    // a3 = h2 @ Wc + bc
    k_gemm3<<<576, 32>>>(Wc, bc);
    // dynamic conv -> cat[:, :2450]
    k_dyn<<<dim3(64, 10), 256>>>(x1, lw, lb);
    // branch b
    k_b1<<<(64 * 4900 + 255) / 256, 256>>>(x2, w5, b5);
    k_b2<<<dim3(64, 51), dim3(32, 8)>>>(w6, b6);
    // z1 = relu(cat @ Wf1 + bf1)
    k_gemm<<<dim3(32, 16), 256>>>(cat, Wf1, part, 15506, 8000, 16);
    k_reduce<<<(64 * 8000 + 255) / 256, 256>>>(bf1, z1, 8000, 16, 1);
    // z2 = relu(z1 @ Wf2 + bf2)
    k_gemm<<<dim3(8, 32), 256>>>(z1, Wf2, part, 8000, 2000, 32);
    k_reduce<<<(64 * 2000 + 255) / 256, 256>>>(bf2, z2, 2000, 32, 1);
    // out = z2 @ Wf3 + bf3
    k_f3<<<128, 32>>>(Wf3, bf3, out);
}